// round 3
// baseline (speedup 1.0000x reference)
#include <cuda_runtime.h>
#include <math.h>

// ---------------------------------------------------------------------------
// SelfAttention: x[8,2048,512] f32
//   Q = x@Wq + bq ; K = x@Wk + bk
//   S = Q@K^T / sqrt(512) ; P = softmax(S, axis=-1) ; out = P @ x
//
// Pipeline (5 launches, serialized on default stream):
//   1) gemm_bias_nn   : Q = x@Wq + bq        [16384,512]
//   2) gemm_bias_nn   : K = x@Wk + bk        [16384,512]
//   3) gemm_nt_scale  : S = scale * Q@K^T    batched [8][2048,2048]
//   4) softmax_rows   : P = softmax(S)       in-place
//   5) gemm_nn_batched: out = P@x            batched [8][2048,512]
// ---------------------------------------------------------------------------

#define BM 128
#define BN 128
#define BK 16
#define TM 8
#define TN 8
#define NTHREADS 256

// Scratch: __device__ globals (allocation-free rule). Q/K: 32MB each, S: 128MB.
__device__ float g_Q[8u * 2048u * 512u];
__device__ float g_K[8u * 2048u * 512u];
__device__ float g_S[8u * 2048u * 2048u];

// ---------------------------------------------------------------------------
// C[M,N] = A[M,K] @ B[K,N] + bias[N]     (A,B,C row-major; all dims % tile == 0)
// ---------------------------------------------------------------------------
__global__ __launch_bounds__(NTHREADS) void gemm_bias_nn(
    const float* __restrict__ A, const float* __restrict__ B,
    const float* __restrict__ bias, float* __restrict__ C,
    int M, int N, int K)
{
    __shared__ float As[BK][BM];
    __shared__ float Bs[BK][BN];
    const int tid = threadIdx.x;
    const int tx = tid & 15;
    const int ty = tid >> 4;
    const int row0 = blockIdx.y * BM;
    const int col0 = blockIdx.x * BN;

    float acc[TM][TN];
#pragma unroll
    for (int i = 0; i < TM; i++)
#pragma unroll
        for (int j = 0; j < TN; j++) acc[i][j] = 0.f;

    for (int k0 = 0; k0 < K; k0 += BK) {
        // A tile [BM x BK] -> As[kk][m] (transposed store)
#pragma unroll
        for (int l = 0; l < 2; l++) {
            int i = tid + l * 256;
            int r = i >> 2;
            int c = (i & 3) << 2;
            float4 v = *(const float4*)(A + (size_t)(row0 + r) * K + k0 + c);
            As[c + 0][r] = v.x; As[c + 1][r] = v.y;
            As[c + 2][r] = v.z; As[c + 3][r] = v.w;
        }
        // B tile [BK x BN] -> Bs[kk][n] (direct, vectorized)
#pragma unroll
        for (int l = 0; l < 2; l++) {
            int i = tid + l * 256;
            int r = i >> 5;
            int c = (i & 31) << 2;
            *(float4*)(&Bs[r][c]) = *(const float4*)(B + (size_t)(k0 + r) * N + col0 + c);
        }
        __syncthreads();
#pragma unroll
        for (int kk = 0; kk < BK; kk++) {
            float a[TM], b[TN];
#pragma unroll
            for (int i = 0; i < TM; i++) a[i] = As[kk][ty * TM + i];
#pragma unroll
            for (int j = 0; j < TN; j++) b[j] = Bs[kk][tx * TN + j];
#pragma unroll
            for (int i = 0; i < TM; i++)
#pragma unroll
                for (int j = 0; j < TN; j++) acc[i][j] = fmaf(a[i], b[j], acc[i][j]);
        }
        __syncthreads();
    }
#pragma unroll
    for (int i = 0; i < TM; i++) {
        int r = row0 + ty * TM + i;
#pragma unroll
        for (int j = 0; j < TN; j += 4) {
            int c = col0 + tx * TN + j;
            float4 v;
            v.x = acc[i][j + 0] + bias[c + 0];
            v.y = acc[i][j + 1] + bias[c + 1];
            v.z = acc[i][j + 2] + bias[c + 2];
            v.w = acc[i][j + 3] + bias[c + 3];
            *(float4*)(C + (size_t)r * N + c) = v;
        }
    }
}

// ---------------------------------------------------------------------------
// Batched: C[z][M,N] = scale * A[z][M,K] @ B[z][N,K]^T
// A,B row-major [M,K]/[N,K]; C row-major [M,N].  (scores: M=N=2048, K=512)
// ---------------------------------------------------------------------------
__global__ __launch_bounds__(NTHREADS) void gemm_nt_scale(
    const float* __restrict__ Ag, const float* __restrict__ Bg,
    float* __restrict__ Cg, int M, int N, int K, float scale)
{
    const float* A = Ag + (size_t)blockIdx.z * M * K;
    const float* B = Bg + (size_t)blockIdx.z * N * K;
    float* C = Cg + (size_t)blockIdx.z * M * N;

    __shared__ float As[BK][BM];
    __shared__ float Bs[BK][BN];
    const int tid = threadIdx.x;
    const int tx = tid & 15;
    const int ty = tid >> 4;
    const int row0 = blockIdx.y * BM;
    const int col0 = blockIdx.x * BN;

    float acc[TM][TN];
#pragma unroll
    for (int i = 0; i < TM; i++)
#pragma unroll
        for (int j = 0; j < TN; j++) acc[i][j] = 0.f;

    for (int k0 = 0; k0 < K; k0 += BK) {
#pragma unroll
        for (int l = 0; l < 2; l++) {
            int i = tid + l * 256;
            int r = i >> 2;
            int c = (i & 3) << 2;
            float4 v = *(const float4*)(A + (size_t)(row0 + r) * K + k0 + c);
            As[c + 0][r] = v.x; As[c + 1][r] = v.y;
            As[c + 2][r] = v.z; As[c + 3][r] = v.w;
        }
        // B^T tile: Bs[kk][n] = B[col0+n][k0+kk]  (transposed store)
#pragma unroll
        for (int l = 0; l < 2; l++) {
            int i = tid + l * 256;
            int r = i >> 2;
            int c = (i & 3) << 2;
            float4 v = *(const float4*)(B + (size_t)(col0 + r) * K + k0 + c);
            Bs[c + 0][r] = v.x; Bs[c + 1][r] = v.y;
            Bs[c + 2][r] = v.z; Bs[c + 3][r] = v.w;
        }
        __syncthreads();
#pragma unroll
        for (int kk = 0; kk < BK; kk++) {
            float a[TM], b[TN];
#pragma unroll
            for (int i = 0; i < TM; i++) a[i] = As[kk][ty * TM + i];
#pragma unroll
            for (int j = 0; j < TN; j++) b[j] = Bs[kk][tx * TN + j];
#pragma unroll
            for (int i = 0; i < TM; i++)
#pragma unroll
                for (int j = 0; j < TN; j++) acc[i][j] = fmaf(a[i], b[j], acc[i][j]);
        }
        __syncthreads();
    }
#pragma unroll
    for (int i = 0; i < TM; i++) {
        int r = row0 + ty * TM + i;
#pragma unroll
        for (int j = 0; j < TN; j += 4) {
            int c = col0 + tx * TN + j;
            float4 v;
            v.x = acc[i][j + 0] * scale;
            v.y = acc[i][j + 1] * scale;
            v.z = acc[i][j + 2] * scale;
            v.w = acc[i][j + 3] * scale;
            *(float4*)(C + (size_t)r * N + c) = v;
        }
    }
}

// ---------------------------------------------------------------------------
// Batched: C[z][M,N] = A[z][M,K] @ B[z][K,N]   (out: M=2048, N=512, K=2048)
// ---------------------------------------------------------------------------
__global__ __launch_bounds__(NTHREADS) void gemm_nn_batched(
    const float* __restrict__ Ag, const float* __restrict__ Bg,
    float* __restrict__ Cg, int M, int N, int K)
{
    const float* A = Ag + (size_t)blockIdx.z * M * K;
    const float* B = Bg + (size_t)blockIdx.z * K * N;
    float* C = Cg + (size_t)blockIdx.z * M * N;

    __shared__ float As[BK][BM];
    __shared__ float Bs[BK][BN];
    const int tid = threadIdx.x;
    const int tx = tid & 15;
    const int ty = tid >> 4;
    const int row0 = blockIdx.y * BM;
    const int col0 = blockIdx.x * BN;

    float acc[TM][TN];
#pragma unroll
    for (int i = 0; i < TM; i++)
#pragma unroll
        for (int j = 0; j < TN; j++) acc[i][j] = 0.f;

    for (int k0 = 0; k0 < K; k0 += BK) {
#pragma unroll
        for (int l = 0; l < 2; l++) {
            int i = tid + l * 256;
            int r = i >> 2;
            int c = (i & 3) << 2;
            float4 v = *(const float4*)(A + (size_t)(row0 + r) * K + k0 + c);
            As[c + 0][r] = v.x; As[c + 1][r] = v.y;
            As[c + 2][r] = v.z; As[c + 3][r] = v.w;
        }
#pragma unroll
        for (int l = 0; l < 2; l++) {
            int i = tid + l * 256;
            int r = i >> 5;
            int c = (i & 31) << 2;
            *(float4*)(&Bs[r][c]) = *(const float4*)(B + (size_t)(k0 + r) * N + col0 + c);
        }
        __syncthreads();
#pragma unroll
        for (int kk = 0; kk < BK; kk++) {
            float a[TM], b[TN];
#pragma unroll
            for (int i = 0; i < TM; i++) a[i] = As[kk][ty * TM + i];
#pragma unroll
            for (int j = 0; j < TN; j++) b[j] = Bs[kk][tx * TN + j];
#pragma unroll
            for (int i = 0; i < TM; i++)
#pragma unroll
                for (int j = 0; j < TN; j++) acc[i][j] = fmaf(a[i], b[j], acc[i][j]);
        }
        __syncthreads();
    }
#pragma unroll
    for (int i = 0; i < TM; i++) {
        int r = row0 + ty * TM + i;
#pragma unroll
        for (int j = 0; j < TN; j += 4) {
            int c = col0 + tx * TN + j;
            float4 v;
            v.x = acc[i][j + 0];
            v.y = acc[i][j + 1];
            v.z = acc[i][j + 2];
            v.w = acc[i][j + 3];
            *(float4*)(C + (size_t)r * N + c) = v;
        }
    }
}

// ---------------------------------------------------------------------------
// In-place row softmax. One CTA per row. N = 2048.
// ---------------------------------------------------------------------------
__global__ __launch_bounds__(NTHREADS) void softmax_rows(float* __restrict__ S, int N)
{
    __shared__ float red[NTHREADS];
    float* p = S + (size_t)blockIdx.x * N;
    const int tid = threadIdx.x;

    float m = -1e30f;
    for (int i = tid; i < N; i += NTHREADS) m = fmaxf(m, p[i]);
    red[tid] = m;
    __syncthreads();
    for (int s = NTHREADS / 2; s > 0; s >>= 1) {
        if (tid < s) red[tid] = fmaxf(red[tid], red[tid + s]);
        __syncthreads();
    }
    m = red[0];
    __syncthreads();

    float sum = 0.f;
    for (int i = tid; i < N; i += NTHREADS) {
        float e = __expf(p[i] - m);
        p[i] = e;
        sum += e;
    }
    red[tid] = sum;
    __syncthreads();
    for (int s = NTHREADS / 2; s > 0; s >>= 1) {
        if (tid < s) red[tid] += red[tid + s];
        __syncthreads();
    }
    float inv = 1.0f / red[0];
    for (int i = tid; i < N; i += NTHREADS) p[i] *= inv;
}

// ---------------------------------------------------------------------------
extern "C" void kernel_launch(void* const* d_in, const int* in_sizes, int n_in,
                              void* d_out, int out_size)
{
    const float* x  = (const float*)d_in[0];  // [8,2048,512]
    const float* Wq = (const float*)d_in[1];  // [512,512]
    const float* bq = (const float*)d_in[2];  // [512]
    const float* Wk = (const float*)d_in[3];  // [512,512]
    const float* bk = (const float*)d_in[4];  // [512]
    float* out = (float*)d_out;               // [8,2048,512]

    float* pQ = nullptr;
    float* pK = nullptr;
    float* pS = nullptr;
    cudaGetSymbolAddress((void**)&pQ, g_Q);
    cudaGetSymbolAddress((void**)&pK, g_K);
    cudaGetSymbolAddress((void**)&pS, g_S);

    const int B = 8, S = 2048, D = 512;
    const int M = B * S;                       // 16384
    const float scale = 1.0f / sqrtf((float)D);

    // 1,2) Q/K projections: [16384,512] = [16384,512]@[512,512] + bias
    {
        dim3 grid(D / BN, M / BM);             // (4, 128)
        gemm_bias_nn<<<grid, NTHREADS>>>(x, Wq, bq, pQ, M, D, D);
        gemm_bias_nn<<<grid, NTHREADS>>>(x, Wk, bk, pK, M, D, D);
    }
    // 3) scores: per batch [2048,2048] = scale * Q@K^T
    {
        dim3 grid(S / BN, S / BM, B);          // (16, 16, 8)
        gemm_nt_scale<<<grid, NTHREADS>>>(pQ, pK, pS, S, S, D, scale);
    }
    // 4) softmax rows (in place)
    softmax_rows<<<M, NTHREADS>>>(pS, S);
    // 5) out: per batch [2048,512] = P @ x
    {
        dim3 grid(D / BN, S / BM, B);          // (4, 16, 8)
        gemm_nn_batched<<<grid, NTHREADS>>>(pS, x, out, S, D, S);
    }
}

// round 6
// speedup vs baseline: 2.4634x; 2.4634x over previous
#include <cuda_runtime.h>
#include <cuda_bf16.h>
#include <cstdint>
#include <math.h>

// ===========================================================================
// SelfAttention via mma.sync (HMMA bf16, base sm_103 ISA — tcgen05 is
// rejected by this harness's ptxas target) with 2-term error-compensated
// splits: X = Xh + Xl (bf16); D = Xh*Yh + Xh*Yl + Xl*Yh (fp32 accum).
//
// Pipeline:
//   prep: split x; transpose+split Wq,Wk; transpose+split x per batch
//   g1:   Qs = (x@Wq + bq)/sqrt(D) -> bf16 planes   [16384,512]
//   g2:   K  = (x@Wk + bk)         -> bf16 planes   [16384,512]
//   g3:   S  = Qs @ K^T            -> fp32          [8][2048,2048]
//   sm:   P  = softmax(S)          -> bf16 planes
//   g4:   out= P @ x               -> fp32 d_out    [8][2048,512]
// ===========================================================================

#define BATCH 8
#define SEQ   2048
#define HID   512
#define MROWS (BATCH * SEQ)   // 16384

// ---------------- scratch (__device__ globals) ----------------
__device__ __nv_bfloat16 g_xh[MROWS * HID];
__device__ __nv_bfloat16 g_xl[MROWS * HID];
__device__ __nv_bfloat16 g_xTh[MROWS * HID];   // per-batch [512,2048]
__device__ __nv_bfloat16 g_xTl[MROWS * HID];
__device__ __nv_bfloat16 g_WqTh[HID * HID];
__device__ __nv_bfloat16 g_WqTl[HID * HID];
__device__ __nv_bfloat16 g_WkTh[HID * HID];
__device__ __nv_bfloat16 g_WkTl[HID * HID];
__device__ __nv_bfloat16 g_Qh[MROWS * HID];
__device__ __nv_bfloat16 g_Ql[MROWS * HID];
__device__ __nv_bfloat16 g_Kh[MROWS * HID];
__device__ __nv_bfloat16 g_Kl[MROWS * HID];
__device__ float         g_S [(size_t)BATCH * SEQ * SEQ];   // 128 MB
__device__ __nv_bfloat16 g_Ph[(size_t)BATCH * SEQ * SEQ];   // 64 MB
__device__ __nv_bfloat16 g_Pl[(size_t)BATCH * SEQ * SEQ];   // 64 MB

// ---------------- mma / ldmatrix helpers (base ISA) ----------------
__device__ __forceinline__ void ldsm_x4(uint32_t* r, uint32_t addr) {
    asm volatile("ldmatrix.sync.aligned.m8n8.x4.shared.b16 {%0,%1,%2,%3}, [%4];"
                 : "=r"(r[0]), "=r"(r[1]), "=r"(r[2]), "=r"(r[3]) : "r"(addr));
}
__device__ __forceinline__ void mma_bf16(float* d, const uint32_t* a, const uint32_t* b) {
    asm volatile(
        "mma.sync.aligned.m16n8k16.row.col.f32.bf16.bf16.f32 "
        "{%0,%1,%2,%3}, {%4,%5,%6,%7}, {%8,%9}, {%0,%1,%2,%3};"
        : "+f"(d[0]), "+f"(d[1]), "+f"(d[2]), "+f"(d[3])
        : "r"(a[0]), "r"(a[1]), "r"(a[2]), "r"(a[3]), "r"(b[0]), "r"(b[1]));
}
__device__ __forceinline__ uint32_t smem_to_u32(const void* p) {
    uint32_t a;
    asm("{ .reg .u64 t; cvta.to.shared.u64 t, %1; cvt.u32.u64 %0, t; }"
        : "=r"(a) : "l"(p));
    return a;
}

// ---------------- prep kernels ----------------
__global__ __launch_bounds__(256) void split_planes(
    const float* __restrict__ src, __nv_bfloat16* __restrict__ h,
    __nv_bfloat16* __restrict__ l, int n)
{
    int i = blockIdx.x * 256 + threadIdx.x;
    if (i < n) {
        float v = src[i];
        __nv_bfloat16 hi = __float2bfloat16(v);
        h[i] = hi;
        l[i] = __float2bfloat16(v - __bfloat162float(hi));
    }
}

// out[c][r] = src[r][c] per batch z, split into planes. block (32,8)
__global__ __launch_bounds__(256) void transpose_split(
    const float* __restrict__ src, __nv_bfloat16* __restrict__ h,
    __nv_bfloat16* __restrict__ l, int R, int C)
{
    __shared__ float t[32][33];
    size_t base = (size_t)blockIdx.z * R * C;
    int c0 = blockIdx.x * 32, r0 = blockIdx.y * 32;
    int tx = threadIdx.x, ty = threadIdx.y;
#pragma unroll
    for (int j = 0; j < 4; j++)
        t[ty + j * 8][tx] = src[base + (size_t)(r0 + ty + j * 8) * C + c0 + tx];
    __syncthreads();
#pragma unroll
    for (int j = 0; j < 4; j++) {
        float v = t[tx][ty + j * 8];
        __nv_bfloat16 hi = __float2bfloat16(v);
        size_t o = base + (size_t)(c0 + ty + j * 8) * R + r0 + tx;
        h[o] = hi;
        l[o] = __float2bfloat16(v - __bfloat162float(hi));
    }
}

// ---------------- softmax: register-resident, emits bf16 hi/lo planes ------
__global__ __launch_bounds__(256) void softmax_split(
    const float* __restrict__ S, __nv_bfloat16* __restrict__ Ph,
    __nv_bfloat16* __restrict__ Pl)
{
    __shared__ float red[256];
    const int tid = threadIdx.x;
    const size_t row = (size_t)blockIdx.x * SEQ;
    const float* p = S + row;

    float v[8];
#pragma unroll
    for (int j = 0; j < 8; j++) v[j] = p[tid + j * 256];

    float m = v[0];
#pragma unroll
    for (int j = 1; j < 8; j++) m = fmaxf(m, v[j]);
    red[tid] = m;
    __syncthreads();
    for (int s = 128; s > 0; s >>= 1) {
        if (tid < s) red[tid] = fmaxf(red[tid], red[tid + s]);
        __syncthreads();
    }
    m = red[0];
    __syncthreads();

    float sum = 0.f;
#pragma unroll
    for (int j = 0; j < 8; j++) {
        v[j] = __expf(v[j] - m);
        sum += v[j];
    }
    red[tid] = sum;
    __syncthreads();
    for (int s = 128; s > 0; s >>= 1) {
        if (tid < s) red[tid] += red[tid + s];
        __syncthreads();
    }
    float inv = 1.0f / red[0];
#pragma unroll
    for (int j = 0; j < 8; j++) {
        float e = v[j] * inv;
        __nv_bfloat16 hi = __float2bfloat16(e);
        Ph[row + tid + j * 256] = hi;
        Pl[row + tid + j * 256] = __float2bfloat16(e - __bfloat162float(hi));
    }
}

// ===========================================================================
// HMMA GEMM: C[M,N] = A[M,K] @ B[N,K]^T, A/B as (hi,lo) bf16 K-major planes.
// CTA tile 128x128, K-chunk 32. 8 warps: warp_m = wid&1 (64 rows),
// warp_n = wid>>1 (32 cols). Per warp: 4x4 m16n8k16 tiles x 3 combos.
// smem: 4 planes [128 rows x 32 halves], row stride 40 halves (80B).
// Epilogue: Cf fp32 (x scale)  OR  (acc+bias)*scale -> (Ch,Cl) planes.
// ===========================================================================
#define PLANE_HALVES (128 * 40)

__global__ __launch_bounds__(256) void gemm_bf16x2(
    const __nv_bfloat16* __restrict__ Ah, const __nv_bfloat16* __restrict__ Al,
    long long sAb,
    const __nv_bfloat16* __restrict__ Bh, const __nv_bfloat16* __restrict__ Bl,
    long long sBb,
    const float* __restrict__ bias, float scale,
    float* __restrict__ Cf,
    __nv_bfloat16* __restrict__ Ch, __nv_bfloat16* __restrict__ Cl,
    long long sCb, int N, int K)
{
    __shared__ __align__(16) __nv_bfloat16 sm4[4 * PLANE_HALVES];  // 40 KB

    const int tid = threadIdx.x;
    const int wid = tid >> 5;
    const int lid = tid & 31;
    const int warp_m = wid & 1;       // 0..1 -> 64-row half
    const int warp_n = wid >> 1;      // 0..3 -> 32-col quarter
    const int row0 = blockIdx.y * 128;
    const int col0 = blockIdx.x * 128;
    const int z = blockIdx.z;

    const __nv_bfloat16* srcs[4];
    srcs[0] = Ah + (size_t)z * sAb + (size_t)row0 * K;
    srcs[1] = Al + (size_t)z * sAb + (size_t)row0 * K;
    srcs[2] = Bh + (size_t)z * sBb + (size_t)col0 * K;
    srcs[3] = Bl + (size_t)z * sBb + (size_t)col0 * K;

    const uint32_t smb = smem_to_u32(sm4);
    const uint32_t pAh = smb;
    const uint32_t pAl = smb + 1 * PLANE_HALVES * 2;
    const uint32_t pBh = smb + 2 * PLANE_HALVES * 2;
    const uint32_t pBl = smb + 3 * PLANE_HALVES * 2;

    // ldmatrix lane addresses (bytes), before kstep/tile offsets:
    // A mats: [m0-7,k0-7],[m8-15,k0-7],[m0-7,k8-15],[m8-15,k8-15]
    const int rA = warp_m * 64 + (lid & 7) + ((lid >> 3) & 1) * 8;
    const uint32_t aoff = (uint32_t)(rA * 40 + ((lid >> 4) & 1) * 8) * 2;
    // B mats: [n0-7,k0-7],[n0-7,k8-15],[n8-15,k0-7],[n8-15,k8-15]
    const int rB = warp_n * 32 + (lid & 7) + ((lid >> 4) & 1) * 8;
    const uint32_t boff = (uint32_t)(rB * 40 + ((lid >> 3) & 1) * 8) * 2;

    float d[4][4][4];
#pragma unroll
    for (int i = 0; i < 4; i++)
#pragma unroll
        for (int j = 0; j < 4; j++)
#pragma unroll
            for (int c = 0; c < 4; c++) d[i][j][c] = 0.f;

    for (int k0 = 0; k0 < K; k0 += 32) {
        // ---- global -> smem: 4 planes x (128 rows x 32 halves) ----
#pragma unroll
        for (int p = 0; p < 4; p++) {
            const __nv_bfloat16* sp = srcs[p];
            uint32_t pb = (uint32_t)(p * PLANE_HALVES * 2);
#pragma unroll
            for (int t = 0; t < 2; t++) {
                int idx = tid + t * 256;          // 0..511
                int r = idx >> 2;
                int ch = idx & 3;                 // 16B chunk
                uint4 v = *(const uint4*)(sp + (size_t)r * K + k0 + ch * 8);
                *(uint4*)((char*)sm4 + pb + r * 80 + ch * 16) = v;
            }
        }
        __syncthreads();

#pragma unroll
        for (int ks = 0; ks < 2; ks++) {
            const uint32_t kb = ks * 32;          // 16 halves = 32 bytes
            uint32_t bh[8], bl[8];
            ldsm_x4(bh + 0, pBh + boff + kb);
            ldsm_x4(bh + 4, pBh + boff + kb + 1280);  // +16 n-rows
            ldsm_x4(bl + 0, pBl + boff + kb);
            ldsm_x4(bl + 4, pBl + boff + kb + 1280);
#pragma unroll
            for (int mi = 0; mi < 4; mi++) {
                uint32_t ah[4], al[4];
                ldsm_x4(ah, pAh + aoff + kb + mi * 1280);
                ldsm_x4(al, pAl + aoff + kb + mi * 1280);
#pragma unroll
                for (int ni = 0; ni < 4; ni++) {
                    mma_bf16(d[mi][ni], ah, bh + ni * 2);
                    mma_bf16(d[mi][ni], ah, bl + ni * 2);
                    mma_bf16(d[mi][ni], al, bh + ni * 2);
                }
            }
        }
        __syncthreads();
    }

    // ---- epilogue ----
    const int tr = lid >> 2;          // 0..7
    const int tc = (lid & 3) * 2;     // 0,2,4,6
#pragma unroll
    for (int mi = 0; mi < 4; mi++) {
        int r0g = row0 + warp_m * 64 + mi * 16 + tr;
#pragma unroll
        for (int ni = 0; ni < 4; ni++) {
            int cg = col0 + warp_n * 32 + ni * 8 + tc;
            if (Cf) {
                float* dst0 = Cf + (size_t)z * sCb + (size_t)r0g * N + cg;
                float* dst1 = dst0 + (size_t)8 * N;
                float2 v0 = make_float2(d[mi][ni][0] * scale, d[mi][ni][1] * scale);
                float2 v1 = make_float2(d[mi][ni][2] * scale, d[mi][ni][3] * scale);
                *(float2*)dst0 = v0;
                *(float2*)dst1 = v1;
            } else {
                float b0 = bias[cg], b1 = bias[cg + 1];
#pragma unroll
                for (int half = 0; half < 2; half++) {
                    float v0 = (d[mi][ni][half * 2 + 0] + b0) * scale;
                    float v1 = (d[mi][ni][half * 2 + 1] + b1) * scale;
                    __nv_bfloat16 h0 = __float2bfloat16(v0);
                    __nv_bfloat16 h1 = __float2bfloat16(v1);
                    __nv_bfloat162 hp; hp.x = h0; hp.y = h1;
                    __nv_bfloat162 lp;
                    lp.x = __float2bfloat16(v0 - __bfloat162float(h0));
                    lp.y = __float2bfloat16(v1 - __bfloat162float(h1));
                    size_t o = (size_t)z * sCb + (size_t)(r0g + half * 8) * N + cg;
                    *(__nv_bfloat162*)(Ch + o) = hp;
                    *(__nv_bfloat162*)(Cl + o) = lp;
                }
            }
        }
    }
}

// ---------------------------------------------------------------------------
extern "C" void kernel_launch(void* const* d_in, const int* in_sizes, int n_in,
                              void* d_out, int out_size)
{
    const float* x  = (const float*)d_in[0];  // [8,2048,512]
    const float* Wq = (const float*)d_in[1];  // [512,512]
    const float* bq = (const float*)d_in[2];  // [512]
    const float* Wk = (const float*)d_in[3];  // [512,512]
    const float* bk = (const float*)d_in[4];  // [512]
    float* out = (float*)d_out;               // [8,2048,512]

    __nv_bfloat16 *xh, *xl, *xTh, *xTl, *WqTh, *WqTl, *WkTh, *WkTl;
    __nv_bfloat16 *Qh, *Ql, *Kh, *Kl, *Ph, *Pl;
    float* Sf;
    cudaGetSymbolAddress((void**)&xh,  g_xh);
    cudaGetSymbolAddress((void**)&xl,  g_xl);
    cudaGetSymbolAddress((void**)&xTh, g_xTh);
    cudaGetSymbolAddress((void**)&xTl, g_xTl);
    cudaGetSymbolAddress((void**)&WqTh, g_WqTh);
    cudaGetSymbolAddress((void**)&WqTl, g_WqTl);
    cudaGetSymbolAddress((void**)&WkTh, g_WkTh);
    cudaGetSymbolAddress((void**)&WkTl, g_WkTl);
    cudaGetSymbolAddress((void**)&Qh,  g_Qh);
    cudaGetSymbolAddress((void**)&Ql,  g_Ql);
    cudaGetSymbolAddress((void**)&Kh,  g_Kh);
    cudaGetSymbolAddress((void**)&Kl,  g_Kl);
    cudaGetSymbolAddress((void**)&Sf,  g_S);
    cudaGetSymbolAddress((void**)&Ph,  g_Ph);
    cudaGetSymbolAddress((void**)&Pl,  g_Pl);

    const float scaleQ = 1.0f / sqrtf((float)HID);

    // --- prep: splits & transposes ---
    split_planes<<<(MROWS * HID + 255) / 256, 256>>>(x, xh, xl, MROWS * HID);
    {
        dim3 g(HID / 32, HID / 32, 1);
        dim3 b(32, 8);
        transpose_split<<<g, b>>>(Wq, WqTh, WqTl, HID, HID);
        transpose_split<<<g, b>>>(Wk, WkTh, WkTl, HID, HID);
    }
    {
        dim3 g(HID / 32, SEQ / 32, BATCH);
        dim3 b(32, 8);
        transpose_split<<<g, b>>>(x, xTh, xTl, SEQ, HID);
    }

    // --- g1/g2: projections (M=16384, N=512, K=512) ---
    {
        dim3 grid(HID / 128, MROWS / 128, 1);
        gemm_bf16x2<<<grid, 256>>>(
            xh, xl, 0, WqTh, WqTl, 0, bq, scaleQ,
            nullptr, Qh, Ql, 0, HID, HID);
        gemm_bf16x2<<<grid, 256>>>(
            xh, xl, 0, WkTh, WkTl, 0, bk, 1.0f,
            nullptr, Kh, Kl, 0, HID, HID);
    }
    // --- g3: scores S = Qs @ K^T (per batch 2048x2048, K=512) ---
    {
        dim3 grid(SEQ / 128, SEQ / 128, BATCH);
        gemm_bf16x2<<<grid, 256>>>(
            Qh, Ql, (long long)SEQ * HID, Kh, Kl, (long long)SEQ * HID,
            nullptr, 1.0f, Sf, nullptr, nullptr, (long long)SEQ * SEQ, SEQ, HID);
    }
    // --- softmax -> P planes ---
    softmax_split<<<MROWS, 256>>>(Sf, Ph, Pl);
    // --- g4: out = P @ x (per batch 2048x512, K=2048) ---
    {
        dim3 grid(HID / 128, SEQ / 128, BATCH);
        gemm_bf16x2<<<grid, 256>>>(
            Ph, Pl, (long long)SEQ * SEQ, xTh, xTl, (long long)HID * SEQ,
            nullptr, 1.0f, out, nullptr, nullptr, (long long)SEQ * HID, HID, SEQ);
    }
}

// round 7
// speedup vs baseline: 2.6502x; 1.0758x over previous
#include <cuda_runtime.h>
#include <cuda_bf16.h>
#include <cstdint>
#include <math.h>

// ===========================================================================
// SelfAttention via mma.sync (HMMA bf16, base sm_103 ISA) with 2-term
// error-compensated splits: X = Xh + Xl (bf16); D = Xh*Yh + Xh*Yl + Xl*Yh.
// R6: cp.async double-buffered GEMM mainloop (overlap gmem with MMA).
// ===========================================================================

#define BATCH 8
#define SEQ   2048
#define HID   512
#define MROWS (BATCH * SEQ)   // 16384

// ---------------- scratch (__device__ globals) ----------------
__device__ __nv_bfloat16 g_xh[MROWS * HID];
__device__ __nv_bfloat16 g_xl[MROWS * HID];
__device__ __nv_bfloat16 g_xTh[MROWS * HID];   // per-batch [512,2048]
__device__ __nv_bfloat16 g_xTl[MROWS * HID];
__device__ __nv_bfloat16 g_WqTh[HID * HID];
__device__ __nv_bfloat16 g_WqTl[HID * HID];
__device__ __nv_bfloat16 g_WkTh[HID * HID];
__device__ __nv_bfloat16 g_WkTl[HID * HID];
__device__ __nv_bfloat16 g_Qh[MROWS * HID];
__device__ __nv_bfloat16 g_Ql[MROWS * HID];
__device__ __nv_bfloat16 g_Kh[MROWS * HID];
__device__ __nv_bfloat16 g_Kl[MROWS * HID];
__device__ float         g_S [(size_t)BATCH * SEQ * SEQ];   // 128 MB
__device__ __nv_bfloat16 g_Ph[(size_t)BATCH * SEQ * SEQ];   // 64 MB
__device__ __nv_bfloat16 g_Pl[(size_t)BATCH * SEQ * SEQ];   // 64 MB

// ---------------- asm helpers (base ISA) ----------------
__device__ __forceinline__ void ldsm_x4(uint32_t* r, uint32_t addr) {
    asm volatile("ldmatrix.sync.aligned.m8n8.x4.shared.b16 {%0,%1,%2,%3}, [%4];"
                 : "=r"(r[0]), "=r"(r[1]), "=r"(r[2]), "=r"(r[3]) : "r"(addr));
}
__device__ __forceinline__ void mma_bf16(float* d, const uint32_t* a, const uint32_t* b) {
    asm volatile(
        "mma.sync.aligned.m16n8k16.row.col.f32.bf16.bf16.f32 "
        "{%0,%1,%2,%3}, {%4,%5,%6,%7}, {%8,%9}, {%0,%1,%2,%3};"
        : "+f"(d[0]), "+f"(d[1]), "+f"(d[2]), "+f"(d[3])
        : "r"(a[0]), "r"(a[1]), "r"(a[2]), "r"(a[3]), "r"(b[0]), "r"(b[1]));
}
__device__ __forceinline__ uint32_t smem_to_u32(const void* p) {
    uint32_t a;
    asm("{ .reg .u64 t; cvta.to.shared.u64 t, %1; cvt.u32.u64 %0, t; }"
        : "=r"(a) : "l"(p));
    return a;
}
__device__ __forceinline__ void cp_async16(uint32_t dst, const void* src) {
    asm volatile("cp.async.cg.shared.global [%0], [%1], 16;"
                 :: "r"(dst), "l"(src));
}
__device__ __forceinline__ void cp_commit() {
    asm volatile("cp.async.commit_group;");
}
template <int N>
__device__ __forceinline__ void cp_wait() {
    asm volatile("cp.async.wait_group %0;" :: "n"(N));
}

// ---------------- prep kernels ----------------
__global__ __launch_bounds__(256) void split_planes(
    const float* __restrict__ src, __nv_bfloat16* __restrict__ h,
    __nv_bfloat16* __restrict__ l, int n)
{
    int i = blockIdx.x * 256 + threadIdx.x;
    if (i < n) {
        float v = src[i];
        __nv_bfloat16 hi = __float2bfloat16(v);
        h[i] = hi;
        l[i] = __float2bfloat16(v - __bfloat162float(hi));
    }
}

__global__ __launch_bounds__(256) void transpose_split(
    const float* __restrict__ src, __nv_bfloat16* __restrict__ h,
    __nv_bfloat16* __restrict__ l, int R, int C)
{
    __shared__ float t[32][33];
    size_t base = (size_t)blockIdx.z * R * C;
    int c0 = blockIdx.x * 32, r0 = blockIdx.y * 32;
    int tx = threadIdx.x, ty = threadIdx.y;
#pragma unroll
    for (int j = 0; j < 4; j++)
        t[ty + j * 8][tx] = src[base + (size_t)(r0 + ty + j * 8) * C + c0 + tx];
    __syncthreads();
#pragma unroll
    for (int j = 0; j < 4; j++) {
        float v = t[tx][ty + j * 8];
        __nv_bfloat16 hi = __float2bfloat16(v);
        size_t o = base + (size_t)(c0 + ty + j * 8) * R + r0 + tx;
        h[o] = hi;
        l[o] = __float2bfloat16(v - __bfloat162float(hi));
    }
}

// ---------------- softmax: register-resident, emits bf16 hi/lo planes ------
__global__ __launch_bounds__(256) void softmax_split(
    const float* __restrict__ S, __nv_bfloat16* __restrict__ Ph,
    __nv_bfloat16* __restrict__ Pl)
{
    __shared__ float red[256];
    const int tid = threadIdx.x;
    const size_t row = (size_t)blockIdx.x * SEQ;
    const float* p = S + row;

    float v[8];
#pragma unroll
    for (int j = 0; j < 8; j++) v[j] = p[tid + j * 256];

    float m = v[0];
#pragma unroll
    for (int j = 1; j < 8; j++) m = fmaxf(m, v[j]);
    red[tid] = m;
    __syncthreads();
    for (int s = 128; s > 0; s >>= 1) {
        if (tid < s) red[tid] = fmaxf(red[tid], red[tid + s]);
        __syncthreads();
    }
    m = red[0];
    __syncthreads();

    float sum = 0.f;
#pragma unroll
    for (int j = 0; j < 8; j++) {
        v[j] = __expf(v[j] - m);
        sum += v[j];
    }
    red[tid] = sum;
    __syncthreads();
    for (int s = 128; s > 0; s >>= 1) {
        if (tid < s) red[tid] += red[tid + s];
        __syncthreads();
    }
    float inv = 1.0f / red[0];
#pragma unroll
    for (int j = 0; j < 8; j++) {
        float e = v[j] * inv;
        __nv_bfloat16 hi = __float2bfloat16(e);
        Ph[row + tid + j * 256] = hi;
        Pl[row + tid + j * 256] = __float2bfloat16(e - __bfloat162float(hi));
    }
}

// ===========================================================================
// HMMA GEMM with 2-stage cp.async double buffer.
// C[M,N] = A[M,K] @ B[N,K]^T, A/B as (hi,lo) bf16 K-major planes.
// CTA tile 128x128, K-chunk 32; 8 warps: warp_m=wid&1 (64 rows),
// warp_n=wid>>1 (32 cols); per warp 4x4 m16n8k16 tiles x 3 combos.
// smem per stage: 4 planes x [128 rows x 32 halves], row stride 80B = 40KB.
// ===========================================================================
#define PLANE_BYTES (128 * 80)            // 10240
#define STAGE_BYTES (4 * PLANE_BYTES)     // 40960
#define GSMEM_TOTAL (2 * STAGE_BYTES)     // 81920

__global__ __launch_bounds__(256) void gemm_bf16x2(
    const __nv_bfloat16* __restrict__ Ah, const __nv_bfloat16* __restrict__ Al,
    long long sAb,
    const __nv_bfloat16* __restrict__ Bh, const __nv_bfloat16* __restrict__ Bl,
    long long sBb,
    const float* __restrict__ bias, float scale,
    float* __restrict__ Cf,
    __nv_bfloat16* __restrict__ Ch, __nv_bfloat16* __restrict__ Cl,
    long long sCb, int N, int K)
{
    extern __shared__ __align__(16) char smem[];

    const int tid = threadIdx.x;
    const int wid = tid >> 5;
    const int lid = tid & 31;
    const int warp_m = wid & 1;
    const int warp_n = wid >> 1;
    const int row0 = blockIdx.y * 128;
    const int col0 = blockIdx.x * 128;
    const int z = blockIdx.z;

    const __nv_bfloat16* srcs[4];
    srcs[0] = Ah + (size_t)z * sAb + (size_t)row0 * K;
    srcs[1] = Al + (size_t)z * sAb + (size_t)row0 * K;
    srcs[2] = Bh + (size_t)z * sBb + (size_t)col0 * K;
    srcs[3] = Bl + (size_t)z * sBb + (size_t)col0 * K;

    const uint32_t smb = smem_to_u32(smem);

    // per-thread cp.async targets: idx = tid + t*256 -> row=idx>>2, chunk=idx&3
    const int ld_r0 = tid >> 2;
    const int ld_ch = tid & 3;

    // ldmatrix lane addresses (bytes) within a plane
    const int rA = warp_m * 64 + (lid & 7) + ((lid >> 3) & 1) * 8;
    const uint32_t aoff = (uint32_t)(rA * 80 + ((lid >> 4) & 1) * 16);
    const int rB = warp_n * 32 + (lid & 7) + ((lid >> 4) & 1) * 8;
    const uint32_t boff = (uint32_t)(rB * 80 + ((lid >> 3) & 1) * 16);

    float d[4][4][4];
#pragma unroll
    for (int i = 0; i < 4; i++)
#pragma unroll
        for (int j = 0; j < 4; j++)
#pragma unroll
            for (int c = 0; c < 4; c++) d[i][j][c] = 0.f;

    const int nchunks = K >> 5;

    // ---- issue loads for chunk `ci` into stage `st` ----
    auto issue = [&](int ci, int st) {
        const int k0 = ci << 5;
        const uint32_t sb = smb + st * STAGE_BYTES;
#pragma unroll
        for (int p = 0; p < 4; p++) {
            const __nv_bfloat16* sp = srcs[p];
            const uint32_t pb = sb + p * PLANE_BYTES;
#pragma unroll
            for (int t = 0; t < 2; t++) {
                int r = ld_r0 + t * 64;
                cp_async16(pb + r * 80 + ld_ch * 16,
                           sp + (size_t)r * K + k0 + ld_ch * 8);
            }
        }
        cp_commit();
    };

    issue(0, 0);

    for (int ci = 0; ci < nchunks; ci++) {
        const int st = ci & 1;
        if (ci + 1 < nchunks) {
            issue(ci + 1, st ^ 1);
            cp_wait<1>();
        } else {
            cp_wait<0>();
        }
        __syncthreads();

        const uint32_t sb = smb + st * STAGE_BYTES;
        const uint32_t pAh = sb;
        const uint32_t pAl = sb + 1 * PLANE_BYTES;
        const uint32_t pBh = sb + 2 * PLANE_BYTES;
        const uint32_t pBl = sb + 3 * PLANE_BYTES;

#pragma unroll
        for (int ks = 0; ks < 2; ks++) {
            const uint32_t kb = ks * 32;
            uint32_t bh[8], bl[8];
            ldsm_x4(bh + 0, pBh + boff + kb);
            ldsm_x4(bh + 4, pBh + boff + kb + 1280);   // +16 n-rows
            ldsm_x4(bl + 0, pBl + boff + kb);
            ldsm_x4(bl + 4, pBl + boff + kb + 1280);
#pragma unroll
            for (int mi = 0; mi < 4; mi++) {
                uint32_t ah[4], al[4];
                ldsm_x4(ah, pAh + aoff + kb + mi * 1280);
                ldsm_x4(al, pAl + aoff + kb + mi * 1280);
#pragma unroll
                for (int ni = 0; ni < 4; ni++) {
                    mma_bf16(d[mi][ni], ah, bh + ni * 2);
                    mma_bf16(d[mi][ni], ah, bl + ni * 2);
                    mma_bf16(d[mi][ni], al, bh + ni * 2);
                }
            }
        }
        __syncthreads();
    }

    // ---- epilogue ----
    const int tr = lid >> 2;
    const int tc = (lid & 3) * 2;
#pragma unroll
    for (int mi = 0; mi < 4; mi++) {
        int r0g = row0 + warp_m * 64 + mi * 16 + tr;
#pragma unroll
        for (int ni = 0; ni < 4; ni++) {
            int cg = col0 + warp_n * 32 + ni * 8 + tc;
            if (Cf) {
                float* dst0 = Cf + (size_t)z * sCb + (size_t)r0g * N + cg;
                float* dst1 = dst0 + (size_t)8 * N;
                float2 v0 = make_float2(d[mi][ni][0] * scale, d[mi][ni][1] * scale);
                float2 v1 = make_float2(d[mi][ni][2] * scale, d[mi][ni][3] * scale);
                *(float2*)dst0 = v0;
                *(float2*)dst1 = v1;
            } else {
                float b0 = bias[cg], b1 = bias[cg + 1];
#pragma unroll
                for (int half = 0; half < 2; half++) {
                    float v0 = (d[mi][ni][half * 2 + 0] + b0) * scale;
                    float v1 = (d[mi][ni][half * 2 + 1] + b1) * scale;
                    __nv_bfloat16 h0 = __float2bfloat16(v0);
                    __nv_bfloat16 h1 = __float2bfloat16(v1);
                    __nv_bfloat162 hp; hp.x = h0; hp.y = h1;
                    __nv_bfloat162 lp;
                    lp.x = __float2bfloat16(v0 - __bfloat162float(h0));
                    lp.y = __float2bfloat16(v1 - __bfloat162float(h1));
                    size_t o = (size_t)z * sCb + (size_t)(r0g + half * 8) * N + cg;
                    *(__nv_bfloat162*)(Ch + o) = hp;
                    *(__nv_bfloat162*)(Cl + o) = lp;
                }
            }
        }
    }
}

// ---------------------------------------------------------------------------
extern "C" void kernel_launch(void* const* d_in, const int* in_sizes, int n_in,
                              void* d_out, int out_size)
{
    const float* x  = (const float*)d_in[0];  // [8,2048,512]
    const float* Wq = (const float*)d_in[1];  // [512,512]
    const float* bq = (const float*)d_in[2];  // [512]
    const float* Wk = (const float*)d_in[3];  // [512,512]
    const float* bk = (const float*)d_in[4];  // [512]
    float* out = (float*)d_out;               // [8,2048,512]

    cudaFuncSetAttribute(gemm_bf16x2,
                         cudaFuncAttributeMaxDynamicSharedMemorySize, GSMEM_TOTAL);

    __nv_bfloat16 *xh, *xl, *xTh, *xTl, *WqTh, *WqTl, *WkTh, *WkTl;
    __nv_bfloat16 *Qh, *Ql, *Kh, *Kl, *Ph, *Pl;
    float* Sf;
    cudaGetSymbolAddress((void**)&xh,  g_xh);
    cudaGetSymbolAddress((void**)&xl,  g_xl);
    cudaGetSymbolAddress((void**)&xTh, g_xTh);
    cudaGetSymbolAddress((void**)&xTl, g_xTl);
    cudaGetSymbolAddress((void**)&WqTh, g_WqTh);
    cudaGetSymbolAddress((void**)&WqTl, g_WqTl);
    cudaGetSymbolAddress((void**)&WkTh, g_WkTh);
    cudaGetSymbolAddress((void**)&WkTl, g_WkTl);
    cudaGetSymbolAddress((void**)&Qh,  g_Qh);
    cudaGetSymbolAddress((void**)&Ql,  g_Ql);
    cudaGetSymbolAddress((void**)&Kh,  g_Kh);
    cudaGetSymbolAddress((void**)&Kl,  g_Kl);
    cudaGetSymbolAddress((void**)&Sf,  g_S);
    cudaGetSymbolAddress((void**)&Ph,  g_Ph);
    cudaGetSymbolAddress((void**)&Pl,  g_Pl);

    const float scaleQ = 1.0f / sqrtf((float)HID);

    // --- prep: splits & transposes ---
    split_planes<<<(MROWS * HID + 255) / 256, 256>>>(x, xh, xl, MROWS * HID);
    {
        dim3 g(HID / 32, HID / 32, 1);
        dim3 b(32, 8);
        transpose_split<<<g, b>>>(Wq, WqTh, WqTl, HID, HID);
        transpose_split<<<g, b>>>(Wk, WkTh, WkTl, HID, HID);
    }
    {
        dim3 g(HID / 32, SEQ / 32, BATCH);
        dim3 b(32, 8);
        transpose_split<<<g, b>>>(x, xTh, xTl, SEQ, HID);
    }

    // --- g1/g2: projections (M=16384, N=512, K=512) ---
    {
        dim3 grid(HID / 128, MROWS / 128, 1);
        gemm_bf16x2<<<grid, 256, GSMEM_TOTAL>>>(
            xh, xl, 0, WqTh, WqTl, 0, bq, scaleQ,
            nullptr, Qh, Ql, 0, HID, HID);
        gemm_bf16x2<<<grid, 256, GSMEM_TOTAL>>>(
            xh, xl, 0, WkTh, WkTl, 0, bk, 1.0f,
            nullptr, Kh, Kl, 0, HID, HID);
    }
    // --- g3: scores S = Qs @ K^T (per batch 2048x2048, K=512) ---
    {
        dim3 grid(SEQ / 128, SEQ / 128, BATCH);
        gemm_bf16x2<<<grid, 256, GSMEM_TOTAL>>>(
            Qh, Ql, (long long)SEQ * HID, Kh, Kl, (long long)SEQ * HID,
            nullptr, 1.0f, Sf, nullptr, nullptr, (long long)SEQ * SEQ, SEQ, HID);
    }
    // --- softmax -> P planes ---
    softmax_split<<<MROWS, 256>>>(Sf, Ph, Pl);
    // --- g4: out = P @ x (per batch 2048x512, K=2048) ---
    {
        dim3 grid(HID / 128, SEQ / 128, BATCH);
        gemm_bf16x2<<<grid, 256, GSMEM_TOTAL>>>(
            Ph, Pl, (long long)SEQ * SEQ, xTh, xTl, (long long)HID * SEQ,
            nullptr, 1.0f, out, nullptr, nullptr, (long long)SEQ * HID, HID, SEQ);
    }
}